// round 15
// baseline (speedup 1.0000x reference)
#include <cuda_runtime.h>
#include <math.h>
#include <stdint.h>

#define D 1024
#define C 16
#define NB 64
#define NBLK (D/NB)      // 16 blocks per dimension
#define NMAX 8192

// ---------------- scratch (static device globals: no allocations allowed) ---
__device__ float g_sigma[C * D * D];              // sigma -> G (chol factor)
__device__ float g_W[C * D * D];                  // W = G^-1 (lower)
__device__ float g_Xs[NMAX * D];                  // X rows gathered by class
__device__ float g_T[C * 512 * 512];              // doubling temp
__device__ float g_Lt[D * D];                     // L^T
__device__ float g_base[D * D];                   // L L^T
__device__ float g_mu[C * D];
__device__ float g_munorm[C];
__device__ int   g_cnt[C];
__device__ int   g_ofs[C];
__device__ int   g_cur[C];
__device__ int   g_idx[NMAX];
__device__ float g_quad[NMAX * C];

__device__ __forceinline__ float to_tf32(float v) {
    uint32_t t;
    asm("cvt.rna.tf32.f32 %0, %1;" : "=r"(t) : "f"(v));
    return __uint_as_float(t);
}

#define MMA_TF32(acc, a0, a1, a2, a3, b0, b1)                                 \
    asm volatile(                                                             \
        "mma.sync.aligned.m16n8k8.row.col.f32.tf32.tf32.f32 "                 \
        "{%0,%1,%2,%3}, {%4,%5,%6,%7}, {%8,%9}, {%0,%1,%2,%3};"               \
        : "+f"(acc[0]), "+f"(acc[1]), "+f"(acc[2]), "+f"(acc[3])              \
        : "r"(a0), "r"(a1), "r"(a2), "r"(a3), "r"(b0), "r"(b1))

// ---------------------------------------------------------------------------
__global__ void k_zero(int mc) {
    int t = blockIdx.x * blockDim.x + threadIdx.x;
    if (t < C) { g_cnt[t] = 0; g_cur[t] = 0; }
    if (t < mc) g_quad[t] = 0.f;
}

__global__ void k_count(const int* __restrict__ y, int n) {
    int t = blockIdx.x * blockDim.x + threadIdx.x;
    if (t < n) atomicAdd(&g_cnt[y[t]], 1);
}

__global__ void k_scan() {
    int s = 0;
    for (int c = 0; c < C; c++) { g_ofs[c] = s; s += g_cnt[c]; }
}

__global__ void k_fill(const int* __restrict__ y, int n) {
    int t = blockIdx.x * blockDim.x + threadIdx.x;
    if (t < n) {
        int c = y[t];
        int pos = atomicAdd(&g_cur[c], 1);
        g_idx[g_ofs[c] + pos] = t;
    }
}

// gather rows of X into class-sorted g_Xs
__global__ void k_gather(const float* __restrict__ X) {
    int b = blockIdx.x;
    int src = g_idx[b];
    const float4* s = (const float4*)&X[(size_t)src * D];
    float4* d = (float4*)&g_Xs[(size_t)b * D];
    for (int t = threadIdx.x; t < D / 4; t += blockDim.x) d[t] = s[t];
}

// per-class column sums -> mu (reads gathered, contiguous rows)
__global__ void k_mu(const float* __restrict__ m, const float* __restrict__ kappa) {
    int c = blockIdx.y;
    int j = blockIdx.x * blockDim.x + threadIdx.x;
    if (j >= D) return;
    int ofs = g_ofs[c], n = g_cnt[c];
    float s = 0.f;
    for (int r = 0; r < n; r++)
        s += g_Xs[(size_t)(ofs + r) * D + j];
    float kap = fabsf(kappa[0]) + 1e-6f;
    g_mu[c * D + j] = (kap * m[j] + s) / (kap + (float)n);
}

__global__ void k_munorm() {
    int c = blockIdx.x, lane = threadIdx.x;
    float s = 0.f;
    for (int k = lane; k < D; k += 32) { float v = g_mu[c * D + k]; s += v * v; }
    for (int o = 16; o; o >>= 1) s += __shfl_xor_sync(0xffffffffu, s, o);
    if (lane == 0) g_munorm[c] = s;
}

// build L^T:  Lt[k*D+i] = (i==k ? |diag_i| : (i>k ? low[i][k] : 0))
__global__ void k_Lt(const float* __restrict__ tdiag, const float* __restrict__ tlow) {
    int e = blockIdx.x * blockDim.x + threadIdx.x;
    if (e >= D * D) return;
    int i = e % D, k = e / D;
    float v = 0.f;
    if (i == k) v = fabsf(tdiag[i]);
    else if (i > k) v = tlow[(size_t)i * D + k];
    g_Lt[e] = v;
}

// ---------------------------------------------------------------------------
// AtA via tensor cores, 3xTF32 split, double-buffered smem + reg prefetch.
// Lower-triangular tiles only (ib >= jb): consumers never read the upper part.
// y < C:  S[c] lower -> g_sigma[c] ;  y == C: base lower -> g_base
#define SKT 16
__global__ __launch_bounds__(256) void k_ssyrk_tc() {
    __shared__ float sAh[2][SKT][132], sAl[2][SKT][132];
    __shared__ float sBh[2][SKT][132], sBl[2][SKT][132];
    int t = blockIdx.x, z = blockIdx.y;
    int a = 0;
    while ((a + 1) * (a + 2) / 2 <= t) a++;
    int b = t - a * (a + 1) / 2;
    int ib = a, jb = b;                       // ib >= jb
    int tid = threadIdx.x, wid = tid >> 5, lane = tid & 31;
    int wm = wid >> 1, wn = wid & 1;
    int gID = lane >> 2, tig = lane & 3;
    int i0 = ib * 128, j0 = jb * 128;
    const float* src;
    float* out;
    int ofs, n;
    if (z < C) { src = g_Xs; ofs = g_ofs[z]; n = g_cnt[z]; out = g_sigma + (size_t)z * D * D; }
    else       { src = g_Lt; ofs = 0;       n = D;        out = g_base; }
    float acc[2][8][4] = {};
    int nchunks = (n + SKT - 1) / SKT;

    int sl_isB[4], sl_rr[4], sl_c4[4];
    #pragma unroll
    for (int l = 0; l < 4; l++) {
        int e = tid + l * 256;
        sl_isB[l] = e >> 9;
        int idx = e & 511;
        sl_rr[l] = idx >> 5;
        sl_c4[l] = (idx & 31) * 4;
    }
    float4 pf[4];

    #define SSYRK_LOAD(R0)                                                     \
        _Pragma("unroll")                                                      \
        for (int l = 0; l < 4; l++) {                                          \
            pf[l] = make_float4(0.f, 0.f, 0.f, 0.f);                           \
            if ((R0) + sl_rr[l] < n) {                                         \
                int col0 = (sl_isB[l] ? j0 : i0) + sl_c4[l];                   \
                pf[l] = *(const float4*)&src[(size_t)(ofs + (R0) + sl_rr[l]) * D + col0]; \
            }                                                                  \
        }

    #define SSYRK_STORE(BUF)                                                   \
        _Pragma("unroll")                                                      \
        for (int l = 0; l < 4; l++) {                                          \
            float* Hh = sl_isB[l] ? &sBh[BUF][sl_rr[l]][sl_c4[l]] : &sAh[BUF][sl_rr[l]][sl_c4[l]]; \
            float* Hl = sl_isB[l] ? &sBl[BUF][sl_rr[l]][sl_c4[l]] : &sAl[BUF][sl_rr[l]][sl_c4[l]]; \
            float h;                                                           \
            h = to_tf32(pf[l].x); Hh[0] = h; Hl[0] = to_tf32(pf[l].x - h);     \
            h = to_tf32(pf[l].y); Hh[1] = h; Hl[1] = to_tf32(pf[l].y - h);     \
            h = to_tf32(pf[l].z); Hh[2] = h; Hl[2] = to_tf32(pf[l].z - h);     \
            h = to_tf32(pf[l].w); Hh[3] = h; Hl[3] = to_tf32(pf[l].w - h);     \
        }

    SSYRK_LOAD(0);
    SSYRK_STORE(0);
    __syncthreads();
    for (int ch = 0; ch < nchunks; ch++) {
        if (ch + 1 < nchunks) { SSYRK_LOAD((ch + 1) * SKT); }
        int buf = ch & 1;
        #pragma unroll
        for (int ks = 0; ks < SKT; ks += 8) {
            uint32_t bh[8][2], bl[8][2];
            #pragma unroll
            for (int nt = 0; nt < 8; nt++) {
                int col = wn * 64 + nt * 8 + gID;
                bh[nt][0] = __float_as_uint(sBh[buf][ks + tig][col]);
                bh[nt][1] = __float_as_uint(sBh[buf][ks + tig + 4][col]);
                bl[nt][0] = __float_as_uint(sBl[buf][ks + tig][col]);
                bl[nt][1] = __float_as_uint(sBl[buf][ks + tig + 4][col]);
            }
            #pragma unroll
            for (int mt = 0; mt < 2; mt++) {
                int row = wm * 32 + mt * 16;
                uint32_t ah0 = __float_as_uint(sAh[buf][ks + tig][row + gID]);
                uint32_t ah1 = __float_as_uint(sAh[buf][ks + tig][row + gID + 8]);
                uint32_t ah2 = __float_as_uint(sAh[buf][ks + tig + 4][row + gID]);
                uint32_t ah3 = __float_as_uint(sAh[buf][ks + tig + 4][row + gID + 8]);
                uint32_t al0 = __float_as_uint(sAl[buf][ks + tig][row + gID]);
                uint32_t al1 = __float_as_uint(sAl[buf][ks + tig][row + gID + 8]);
                uint32_t al2 = __float_as_uint(sAl[buf][ks + tig + 4][row + gID]);
                uint32_t al3 = __float_as_uint(sAl[buf][ks + tig + 4][row + gID + 8]);
                #pragma unroll
                for (int nt = 0; nt < 8; nt++) {
                    MMA_TF32(acc[mt][nt], ah0, ah1, ah2, ah3, bh[nt][0], bh[nt][1]);
                    MMA_TF32(acc[mt][nt], ah0, ah1, ah2, ah3, bl[nt][0], bl[nt][1]);
                    MMA_TF32(acc[mt][nt], al0, al1, al2, al3, bh[nt][0], bh[nt][1]);
                }
            }
        }
        __syncthreads();
        if (ch + 1 < nchunks) {
            SSYRK_STORE((ch + 1) & 1);
            __syncthreads();
        }
    }
    #pragma unroll
    for (int mt = 0; mt < 2; mt++)
        #pragma unroll
        for (int nt = 0; nt < 8; nt++) {
            int row = i0 + wm * 32 + mt * 16 + gID;
            int col = j0 + wn * 64 + nt * 8 + tig * 2;
            out[(size_t)row * D + col]           = acc[mt][nt][0];
            out[(size_t)row * D + col + 1]       = acc[mt][nt][1];
            out[(size_t)(row + 8) * D + col]     = acc[mt][nt][2];
            out[(size_t)(row + 8) * D + col + 1] = acc[mt][nt][3];
        }
}

// sigma = (S + base + kap m m^T - (kap+Nj) mu mu^T) / (nu_ + Nj + d + 2)
// lower triangle only — downstream never reads the upper part.
__global__ void k_assemble(const float* __restrict__ m,
                           const float* __restrict__ kappa,
                           const float* __restrict__ nu) {
    int c = blockIdx.y;
    int e = blockIdx.x * blockDim.x + threadIdx.x;
    if (e >= D * D) return;
    int i = e / D, j = e % D;
    if (j > i) return;
    float kap = fabsf(kappa[0]) + 1e-6f;
    float nj = (float)g_cnt[c];
    float nu_ = fmaxf(nu[0], (float)(D - 1) + 1e-6f);
    float scale = 1.f / (nu_ + nj + (float)D + 2.f);
    float coef = kap + nj;
    size_t o = (size_t)c * D * D + e;
    g_sigma[o] = (g_sigma[o] + g_base[e] + kap * m[i] * m[j]
                  - coef * g_mu[c * D + i] * g_mu[c * D + j]) * scale;
}

// Cholesky factor of the 64x64 diag block (used only for tile (0,0))
__global__ void k_potf2(int kstep) {
    __shared__ float As[NB][NB + 1];
    int c = blockIdx.x, tid = threadIdx.x;
    size_t base = (size_t)c * D * D + (size_t)(kstep * NB) * D + kstep * NB;
    for (int e = tid; e < NB * NB; e += 64)
        As[e / 64][e % 64] = g_sigma[base + (size_t)(e / 64) * D + (e % 64)];
    __syncthreads();
    for (int j = 0; j < NB; j++) {
        if (tid == 0) As[j][j] = sqrtf(As[j][j]);
        __syncthreads();
        if (tid > j) As[tid][j] = As[tid][j] / As[j][j];
        __syncthreads();
        if (tid > j) {
            float l = As[tid][j];
            for (int p = j + 1; p <= tid; p++) As[tid][p] -= l * As[p][j];
        }
        __syncthreads();
    }
    for (int e = tid; e < NB * NB; e += 64) {
        int r = e / 64, cc = e % 64;
        g_sigma[base + (size_t)r * D + cc] = (r >= cc) ? As[r][cc] : 0.f;
    }
}

// panel tile (i,kstep): A <- A * Gkk^{-T} by direct forward substitution
__global__ __launch_bounds__(256) void k_trsolve(int kstep) {
    __shared__ float sG[NB][NB + 1], sX[NB][NB + 1], rd[NB];
    int i = kstep + 1 + blockIdx.x, c = blockIdx.y;
    int tid = threadIdx.x, r = tid & 63, g = tid >> 6;
    size_t gb = (size_t)c * D * D + (size_t)(kstep * NB) * D + kstep * NB;
    size_t ab = (size_t)c * D * D + (size_t)(i * NB) * D + kstep * NB;
    for (int e = tid; e < NB * NB; e += 256) {
        sG[e / 64][e % 64] = g_sigma[gb + (size_t)(e / 64) * D + (e % 64)];
        sX[e / 64][e % 64] = g_sigma[ab + (size_t)(e / 64) * D + (e % 64)];
    }
    __syncthreads();
    if (tid < NB) rd[tid] = 1.f / sG[tid][tid];
    __syncthreads();
    for (int j = 0; j < NB; j++) {
        if (g == 0) sX[r][j] *= rd[j];
        __syncthreads();
        float xj = sX[r][j];
        for (int p = j + 1 + g; p < NB; p += 4)
            sX[r][p] -= xj * sG[p][j];
        __syncthreads();
    }
    for (int e = tid; e < NB * NB; e += 256)
        g_sigma[ab + (size_t)(e / 64) * D + (e % 64)] = sX[e / 64][e % 64];
}

// trailing update: A[i][j] -= Panel_i Panel_j^T (tensor, 3xTF32, 64x64 tiles).
// Block t==0 additionally factors tile (k+1,k+1) after its final update,
// removing the separate potf2 launch from the serial chain.
__global__ __launch_bounds__(128) void k_syrkstep_tc(int kstep) {
    __shared__ float sAh[64][20], sAl[64][20], sBh[64][20], sBl[64][20];
    __shared__ float Fs[NB][NB + 1];
    int t = blockIdx.x, c = blockIdx.y;
    int a = 0;
    while ((a + 1) * (a + 2) / 2 <= t) a++;
    int b = t - a * (a + 1) / 2;
    int i = kstep + 1 + a, j = kstep + 1 + b;
    int tid = threadIdx.x, wid = tid >> 5, lane = tid & 31;
    int wm = wid >> 1, wn = wid & 1;
    int gID = lane >> 2, tig = lane & 3;
    size_t ik = (size_t)c * D * D + (size_t)(i * NB) * D + kstep * NB;
    size_t jk = (size_t)c * D * D + (size_t)(j * NB) * D + kstep * NB;
    size_t ij = (size_t)c * D * D + (size_t)(i * NB) * D + j * NB;
    float acc[2][4][4] = {};
    for (int k0 = 0; k0 < NB; k0 += 16) {
        #pragma unroll
        for (int l = 0; l < 2; l++) {
            int e = tid + l * 128;
            int row = e >> 2, k4 = (e & 3) * 4;
            float4 v = *(const float4*)&g_sigma[ik + (size_t)row * D + k0 + k4];
            float h;
            h = to_tf32(v.x); sAh[row][k4 + 0] = h; sAl[row][k4 + 0] = to_tf32(v.x - h);
            h = to_tf32(v.y); sAh[row][k4 + 1] = h; sAl[row][k4 + 1] = to_tf32(v.y - h);
            h = to_tf32(v.z); sAh[row][k4 + 2] = h; sAl[row][k4 + 2] = to_tf32(v.z - h);
            h = to_tf32(v.w); sAh[row][k4 + 3] = h; sAl[row][k4 + 3] = to_tf32(v.w - h);
            float4 w = *(const float4*)&g_sigma[jk + (size_t)row * D + k0 + k4];
            h = to_tf32(w.x); sBh[row][k4 + 0] = h; sBl[row][k4 + 0] = to_tf32(w.x - h);
            h = to_tf32(w.y); sBh[row][k4 + 1] = h; sBl[row][k4 + 1] = to_tf32(w.y - h);
            h = to_tf32(w.z); sBh[row][k4 + 2] = h; sBl[row][k4 + 2] = to_tf32(w.z - h);
            h = to_tf32(w.w); sBh[row][k4 + 3] = h; sBl[row][k4 + 3] = to_tf32(w.w - h);
        }
        __syncthreads();
        #pragma unroll
        for (int ks = 0; ks < 16; ks += 8) {
            uint32_t bh[4][2], bl[4][2];
            #pragma unroll
            for (int nt = 0; nt < 4; nt++) {
                int nb = wn * 32 + nt * 8 + gID;
                bh[nt][0] = __float_as_uint(sBh[nb][ks + tig]);
                bh[nt][1] = __float_as_uint(sBh[nb][ks + tig + 4]);
                bl[nt][0] = __float_as_uint(sBl[nb][ks + tig]);
                bl[nt][1] = __float_as_uint(sBl[nb][ks + tig + 4]);
            }
            #pragma unroll
            for (int mt = 0; mt < 2; mt++) {
                int mr = wm * 32 + mt * 16 + gID;
                uint32_t ah0 = __float_as_uint(sAh[mr][ks + tig]);
                uint32_t ah1 = __float_as_uint(sAh[mr + 8][ks + tig]);
                uint32_t ah2 = __float_as_uint(sAh[mr][ks + tig + 4]);
                uint32_t ah3 = __float_as_uint(sAh[mr + 8][ks + tig + 4]);
                uint32_t al0 = __float_as_uint(sAl[mr][ks + tig]);
                uint32_t al1 = __float_as_uint(sAl[mr + 8][ks + tig]);
                uint32_t al2 = __float_as_uint(sAl[mr][ks + tig + 4]);
                uint32_t al3 = __float_as_uint(sAl[mr + 8][ks + tig + 4]);
                #pragma unroll
                for (int nt = 0; nt < 4; nt++) {
                    MMA_TF32(acc[mt][nt], ah0, ah1, ah2, ah3, bh[nt][0], bh[nt][1]);
                    MMA_TF32(acc[mt][nt], ah0, ah1, ah2, ah3, bl[nt][0], bl[nt][1]);
                    MMA_TF32(acc[mt][nt], al0, al1, al2, al3, bh[nt][0], bh[nt][1]);
                }
            }
        }
        __syncthreads();
    }
    #pragma unroll
    for (int mt = 0; mt < 2; mt++)
        #pragma unroll
        for (int nt = 0; nt < 4; nt++) {
            int row = wm * 32 + mt * 16 + gID;
            int col = wn * 32 + nt * 8 + tig * 2;
            size_t o0 = ij + (size_t)row * D + col;
            size_t o1 = ij + (size_t)(row + 8) * D + col;
            g_sigma[o0]     -= acc[mt][nt][0];
            g_sigma[o0 + 1] -= acc[mt][nt][1];
            g_sigma[o1]     -= acc[mt][nt][2];
            g_sigma[o1 + 1] -= acc[mt][nt][3];
        }
    // ---- fused potf2 for the next step's diagonal tile (t == 0: i=j=k+1) ----
    if (t == 0) {
        __syncthreads();
        for (int e = tid; e < NB * NB; e += 128)
            Fs[e >> 6][e & 63] = g_sigma[ij + (size_t)(e >> 6) * D + (e & 63)];
        __syncthreads();
        for (int jj = 0; jj < NB; jj++) {
            if (tid == 0) Fs[jj][jj] = sqrtf(Fs[jj][jj]);
            __syncthreads();
            if (tid > jj && tid < NB) Fs[tid][jj] = Fs[tid][jj] / Fs[jj][jj];
            __syncthreads();
            if (tid > jj && tid < NB) {
                float l = Fs[tid][jj];
                for (int p = jj + 1; p <= tid; p++) Fs[tid][p] -= l * Fs[p][jj];
            }
            __syncthreads();
        }
        for (int e = tid; e < NB * NB; e += 128) {
            int r = e >> 6, cc = e & 63;
            g_sigma[ij + (size_t)r * D + cc] = (r >= cc) ? Fs[r][cc] : 0.f;
        }
    }
}

// zero all of W (upper blocks must read as true zeros)
__global__ void k_wzero() {
    size_t t = (size_t)blockIdx.x * blockDim.x + threadIdx.x;
    float4 z = make_float4(0.f, 0.f, 0.f, 0.f);
    ((float4*)g_W)[t] = z;
}

// all 64x64 diag-block triangular inverses -> W diag blocks (one launch)
__global__ void k_tinv() {
    __shared__ float As[NB][NB + 1], Inv[NB][NB + 1];
    int kk = blockIdx.x, c = blockIdx.y, tid = threadIdx.x;
    size_t base = (size_t)c * D * D + (size_t)(kk * NB) * D + kk * NB;
    for (int e = tid; e < NB * NB; e += 64) {
        As[e / 64][e % 64] = g_sigma[base + (size_t)(e / 64) * D + (e % 64)];
        Inv[e / 64][e % 64] = 0.f;
    }
    __syncthreads();
    {
        int cc = tid;
        for (int i = cc; i < NB; i++) {
            float s = (i == cc) ? 1.f : 0.f;
            for (int p = cc; p < i; p++) s -= As[i][p] * Inv[p][cc];
            Inv[i][cc] = s / As[i][i];
        }
    }
    __syncthreads();
    for (int e = tid; e < NB * NB; e += 64)
        g_W[base + (size_t)(e / 64) * D + (e % 64)] = Inv[e / 64][e % 64];
}

// -------- recursive-doubling block inverse (tensor, 3xTF32) ----------------
// phase 0: T = G21 * W11  (W11 lower => k starts at tj*64)
// phase 1: W21 = -W22 * T (W22 lower => k ends at (ti+1)*64)
__global__ __launch_bounds__(128) void k_dblmm(int s, int npairs, int phase) {
    __shared__ float sAh[64][20], sAl[64][20];
    __shared__ float sBh[16][68], sBl[16][68];
    int z = blockIdx.z, c = z / npairs, p = z % npairs;
    int ti = blockIdx.x, tj = blockIdx.y;
    int o = p * 2 * s;
    int tid = threadIdx.x, wid = tid >> 5, lane = tid & 31;
    int wm = wid >> 1, wn = wid & 1;
    int gID = lane >> 2, tig = lane & 3;
    const float* Arow;
    const float* Bbase;
    int ldB;
    float* T = g_T + ((size_t)(c * npairs + p)) * s * s;
    if (phase == 0) {
        Arow  = g_sigma + (size_t)c * D * D + (size_t)(o + s + ti * 64) * D + o;
        Bbase = g_W + (size_t)c * D * D + (size_t)o * D + o + tj * 64;
        ldB = D;
    } else {
        Arow  = g_W + (size_t)c * D * D + (size_t)(o + s + ti * 64) * D + (o + s);
        Bbase = T + tj * 64;
        ldB = s;
    }
    int klo = (phase == 0) ? tj * 64 : 0;
    int khi = (phase == 0) ? s : ((ti + 1) * 64 < s ? (ti + 1) * 64 : s);
    float acc[2][4][4] = {};
    for (int k0 = klo; k0 < khi; k0 += 16) {
        #pragma unroll
        for (int l = 0; l < 2; l++) {
            int e = tid + l * 128;
            int row = e >> 2, k4 = (e & 3) * 4;
            float4 v = *(const float4*)&Arow[(size_t)row * D + k0 + k4];
            float h;
            h = to_tf32(v.x); sAh[row][k4 + 0] = h; sAl[row][k4 + 0] = to_tf32(v.x - h);
            h = to_tf32(v.y); sAh[row][k4 + 1] = h; sAl[row][k4 + 1] = to_tf32(v.y - h);
            h = to_tf32(v.z); sAh[row][k4 + 2] = h; sAl[row][k4 + 2] = to_tf32(v.z - h);
            h = to_tf32(v.w); sAh[row][k4 + 3] = h; sAl[row][k4 + 3] = to_tf32(v.w - h);
            int kk = e >> 4, n4 = (e & 15) * 4;
            float4 w = *(const float4*)&Bbase[(size_t)(k0 + kk) * ldB + n4];
            h = to_tf32(w.x); sBh[kk][n4 + 0] = h; sBl[kk][n4 + 0] = to_tf32(w.x - h);
            h = to_tf32(w.y); sBh[kk][n4 + 1] = h; sBl[kk][n4 + 1] = to_tf32(w.y - h);
            h = to_tf32(w.z); sBh[kk][n4 + 2] = h; sBl[kk][n4 + 2] = to_tf32(w.z - h);
            h = to_tf32(w.w); sBh[kk][n4 + 3] = h; sBl[kk][n4 + 3] = to_tf32(w.w - h);
        }
        __syncthreads();
        #pragma unroll
        for (int ks = 0; ks < 16; ks += 8) {
            uint32_t bh[4][2], bl[4][2];
            #pragma unroll
            for (int nt = 0; nt < 4; nt++) {
                int col = wn * 32 + nt * 8 + gID;
                bh[nt][0] = __float_as_uint(sBh[ks + tig][col]);
                bh[nt][1] = __float_as_uint(sBh[ks + tig + 4][col]);
                bl[nt][0] = __float_as_uint(sBl[ks + tig][col]);
                bl[nt][1] = __float_as_uint(sBl[ks + tig + 4][col]);
            }
            #pragma unroll
            for (int mt = 0; mt < 2; mt++) {
                int mr = wm * 32 + mt * 16 + gID;
                uint32_t ah0 = __float_as_uint(sAh[mr][ks + tig]);
                uint32_t ah1 = __float_as_uint(sAh[mr + 8][ks + tig]);
                uint32_t ah2 = __float_as_uint(sAh[mr][ks + tig + 4]);
                uint32_t ah3 = __float_as_uint(sAh[mr + 8][ks + tig + 4]);
                uint32_t al0 = __float_as_uint(sAl[mr][ks + tig]);
                uint32_t al1 = __float_as_uint(sAl[mr + 8][ks + tig]);
                uint32_t al2 = __float_as_uint(sAl[mr][ks + tig + 4]);
                uint32_t al3 = __float_as_uint(sAl[mr + 8][ks + tig + 4]);
                #pragma unroll
                for (int nt = 0; nt < 4; nt++) {
                    MMA_TF32(acc[mt][nt], ah0, ah1, ah2, ah3, bh[nt][0], bh[nt][1]);
                    MMA_TF32(acc[mt][nt], ah0, ah1, ah2, ah3, bl[nt][0], bl[nt][1]);
                    MMA_TF32(acc[mt][nt], al0, al1, al2, al3, bh[nt][0], bh[nt][1]);
                }
            }
        }
        __syncthreads();
    }
    if (phase == 0) {
        #pragma unroll
        for (int mt = 0; mt < 2; mt++)
            #pragma unroll
            for (int nt = 0; nt < 4; nt++) {
                int row = ti * 64 + wm * 32 + mt * 16 + gID;
                int col = tj * 64 + wn * 32 + nt * 8 + tig * 2;
                T[(size_t)row * s + col]           = acc[mt][nt][0];
                T[(size_t)row * s + col + 1]       = acc[mt][nt][1];
                T[(size_t)(row + 8) * s + col]     = acc[mt][nt][2];
                T[(size_t)(row + 8) * s + col + 1] = acc[mt][nt][3];
            }
    } else {
        float* Wout = g_W + (size_t)c * D * D;
        #pragma unroll
        for (int mt = 0; mt < 2; mt++)
            #pragma unroll
            for (int nt = 0; nt < 4; nt++) {
                int row = o + s + ti * 64 + wm * 32 + mt * 16 + gID;
                int col = o + tj * 64 + wn * 32 + nt * 8 + tig * 2;
                Wout[(size_t)row * D + col]           = -acc[mt][nt][0];
                Wout[(size_t)row * D + col + 1]       = -acc[mt][nt][1];
                Wout[(size_t)(row + 8) * D + col]     = -acc[mt][nt][2];
                Wout[(size_t)(row + 8) * D + col + 1] = -acc[mt][nt][3];
            }
    }
}

// ---------------------------------------------------------------------------
// Y = d @ W^T restricted to i-strip; accumulate sum_i Y[q][i]^2 into g_quad.
// Double-buffered smem + register prefetch to hide global latency.
#define QT 128
#define KT 32
__global__ __launch_bounds__(256) void k_ymm(const float* __restrict__ Xq, int M) {
    __shared__ float sD[2][QT][KT + 4];
    __shared__ float sW[2][QT][KT + 4];
    int qb = blockIdx.x, jb = blockIdx.y, c = blockIdx.z;
    int tid = threadIdx.x;
    int wid = tid >> 5, lane = tid & 31;
    int wm = wid >> 1, wn = wid & 1;
    int gID = lane >> 2, tig = lane & 3;
    int q0 = qb * QT, i0 = jb * QT;
    const float* W = g_W + (size_t)c * D * D;
    const float* muc = g_mu + c * D;
    int nchunks = (jb + 1) * QT / KT;
    float acc[2][8][4] = {};

    int sl_r[4], sl_kk[4];
    #pragma unroll
    for (int l = 0; l < 4; l++) {
        int e = tid + l * 256;
        sl_r[l] = e >> 3;
        sl_kk[l] = (e & 7) * 4;
    }
    float4 pD[4], pM[4], pW[4];

    #define YMM_LOAD(K0)                                                       \
        _Pragma("unroll")                                                      \
        for (int l = 0; l < 4; l++) {                                          \
            pD[l] = *(const float4*)&Xq[(size_t)(q0 + sl_r[l]) * D + (K0) + sl_kk[l]]; \
            pM[l] = *(const float4*)&muc[(K0) + sl_kk[l]];                     \
            pW[l] = *(const float4*)&W[(size_t)(i0 + sl_r[l]) * D + (K0) + sl_kk[l]];  \
        }

    #define YMM_STORE(BUF)                                                     \
        _Pragma("unroll")                                                      \
        for (int l = 0; l < 4; l++) {                                          \
            float* pd = &sD[BUF][sl_r[l]][sl_kk[l]];                           \
            float* pw = &sW[BUF][sl_r[l]][sl_kk[l]];                           \
            pd[0] = to_tf32(pD[l].x - pM[l].x);                                \
            pd[1] = to_tf32(pD[l].y - pM[l].y);                                \
            pd[2] = to_tf32(pD[l].z - pM[l].z);                                \
            pd[3] = to_tf32(pD[l].w - pM[l].w);                                \
            pw[0] = to_tf32(pW[l].x);                                          \
            pw[1] = to_tf32(pW[l].y);                                          \
            pw[2] = to_tf32(pW[l].z);                                          \
            pw[3] = to_tf32(pW[l].w);                                          \
        }

    YMM_LOAD(0);
    YMM_STORE(0);
    __syncthreads();
    for (int ch = 0; ch < nchunks; ch++) {
        if (ch + 1 < nchunks) { YMM_LOAD((ch + 1) * KT); }
        int buf = ch & 1;
        #pragma unroll
        for (int ks = 0; ks < KT; ks += 8) {
            uint32_t bf[8][2];
            #pragma unroll
            for (int nt = 0; nt < 8; nt++) {
                int nb = wn * 64 + nt * 8 + gID;
                bf[nt][0] = __float_as_uint(sW[buf][nb][ks + tig]);
                bf[nt][1] = __float_as_uint(sW[buf][nb][ks + tig + 4]);
            }
            #pragma unroll
            for (int mt = 0; mt < 2; mt++) {
                int r = wm * 32 + mt * 16 + gID;
                uint32_t a0 = __float_as_uint(sD[buf][r][ks + tig]);
                uint32_t a1 = __float_as_uint(sD[buf][r + 8][ks + tig]);
                uint32_t a2 = __float_as_uint(sD[buf][r][ks + tig + 4]);
                uint32_t a3 = __float_as_uint(sD[buf][r + 8][ks + tig + 4]);
                #pragma unroll
                for (int nt = 0; nt < 8; nt++) {
                    MMA_TF32(acc[mt][nt], a0, a1, a2, a3, bf[nt][0], bf[nt][1]);
                }
            }
        }
        __syncthreads();
        if (ch + 1 < nchunks) {
            YMM_STORE((ch + 1) & 1);
            __syncthreads();
        }
    }
    float rs[2][2];
    #pragma unroll
    for (int mt = 0; mt < 2; mt++) {
        rs[mt][0] = 0.f; rs[mt][1] = 0.f;
        #pragma unroll
        for (int nt = 0; nt < 8; nt++) {
            rs[mt][0] += acc[mt][nt][0] * acc[mt][nt][0] + acc[mt][nt][1] * acc[mt][nt][1];
            rs[mt][1] += acc[mt][nt][2] * acc[mt][nt][2] + acc[mt][nt][3] * acc[mt][nt][3];
        }
    }
    #pragma unroll
    for (int o = 1; o <= 2; o <<= 1) {
        rs[0][0] += __shfl_xor_sync(0xffffffffu, rs[0][0], o);
        rs[0][1] += __shfl_xor_sync(0xffffffffu, rs[0][1], o);
        rs[1][0] += __shfl_xor_sync(0xffffffffu, rs[1][0], o);
        rs[1][1] += __shfl_xor_sync(0xffffffffu, rs[1][1], o);
    }
    if (tig == 0) {
        #pragma unroll
        for (int mt = 0; mt < 2; mt++) {
            #pragma unroll
            for (int h = 0; h < 2; h++) {
                int q = q0 + wm * 32 + mt * 16 + gID + h * 8;
                atomicAdd(&g_quad[(size_t)q * C + c], rs[mt][h]);
            }
        }
    }
}

// out[q][c] = -(0.9*quad + 0.1*(||x||^2 - 2 x.mu + ||mu||^2))
__global__ __launch_bounds__(256) void k_final(const float* __restrict__ Xq,
                                               float* __restrict__ out) {
    __shared__ float sx[D];
    __shared__ float sqn[8];
    int q = blockIdx.x, tid = threadIdx.x, wid = tid >> 5, lane = tid & 31;
    const float* xr = Xq + (size_t)q * D;
    float pn = 0.f;
    for (int k = tid; k < D; k += 256) { float v = xr[k]; sx[k] = v; pn += v * v; }
    for (int o = 16; o; o >>= 1) pn += __shfl_xor_sync(0xffffffffu, pn, o);
    if (lane == 0) sqn[wid] = pn;
    __syncthreads();
    float qn = 0.f;
    #pragma unroll
    for (int w = 0; w < 8; w++) qn += sqn[w];
    for (int c = wid; c < C; c += 8) {
        const float* muc = g_mu + c * D;
        float ds = 0.f;
        for (int k = lane; k < D; k += 32) ds += sx[k] * muc[k];
        for (int o = 16; o; o >>= 1) ds += __shfl_xor_sync(0xffffffffu, ds, o);
        if (lane == 0) {
            float n2 = qn - 2.f * ds + g_munorm[c];
            out[(size_t)q * C + c] = -(0.9f * g_quad[(size_t)q * C + c] + 0.1f * n2);
        }
    }
}

// ---------------------------------------------------------------------------
extern "C" void kernel_launch(void* const* d_in, const int* in_sizes, int n_in,
                              void* d_out, int out_size) {
    const float* X     = (const float*)d_in[0];
    const int*   y     = (const int*)  d_in[1];
    const float* Xq    = (const float*)d_in[2];
    const float* m     = (const float*)d_in[3];
    const float* kappa = (const float*)d_in[4];
    const float* nu    = (const float*)d_in[5];
    const float* tdiag = (const float*)d_in[6];
    const float* tlow  = (const float*)d_in[7];
    float* out = (float*)d_out;
    int N = in_sizes[1];
    int M = in_sizes[2] / D;

    k_zero<<<(M * C + 255) / 256, 256>>>(M * C);
    k_count<<<(N + 255) / 256, 256>>>(y, N);
    k_scan<<<1, 1>>>();
    k_fill<<<(N + 255) / 256, 256>>>(y, N);
    k_gather<<<N, 256>>>(X);
    k_mu<<<dim3((D + 255) / 256, C), 256>>>(m, kappa);
    k_munorm<<<C, 32>>>();
    k_Lt<<<(D * D + 255) / 256, 256>>>(tdiag, tlow);
    k_ssyrk_tc<<<dim3(36, C + 1), 256>>>();                 // lower tiles only
    k_assemble<<<dim3(D * D / 256, C), 256>>>(m, kappa, nu);

    k_wzero<<<(C * D * D / 4) / 256, 256>>>();
    k_potf2<<<C, 64>>>(0);
    for (int k = 0; k < NBLK; k++) {
        int rows = NBLK - 1 - k;
        if (rows > 0) {
            k_trsolve<<<dim3(rows, C), 256>>>(k);
            // t==0 block also factors tile (k+1,k+1) after updating it
            k_syrkstep_tc<<<dim3(rows * (rows + 1) / 2, C), 128>>>(k);
        }
    }
    k_tinv<<<dim3(NBLK, C), 64>>>();
    for (int l = 0; l < 4; l++) {
        int s = 64 << l;
        int npairs = D / (2 * s);
        k_dblmm<<<dim3(s / 64, s / 64, C * npairs), 128>>>(s, npairs, 0);
        k_dblmm<<<dim3(s / 64, s / 64, C * npairs), 128>>>(s, npairs, 1);
    }

    k_ymm<<<dim3(M / QT, D / QT, C), 256>>>(Xq, M);
    k_final<<<M, 256>>>(Xq, out);
}

// round 16
// speedup vs baseline: 1.5202x; 1.5202x over previous
#include <cuda_runtime.h>
#include <math.h>
#include <stdint.h>

#define D 1024
#define C 16
#define NB 64
#define NBLK (D/NB)      // 16 blocks per dimension
#define NMAX 8192

// ---------------- scratch (static device globals: no allocations allowed) ---
__device__ float g_sigma[C * D * D];              // sigma -> G (chol factor)
__device__ float g_W[C * D * D];                  // W = G^-1 (lower)
__device__ float g_Xs[NMAX * D];                  // X rows gathered by class
__device__ float g_T[C * 512 * 512];              // doubling temp
__device__ float g_Lt[D * D];                     // L^T
__device__ float g_base[D * D];                   // L L^T
__device__ float g_mu[C * D];
__device__ float g_munorm[C];
__device__ int   g_cnt[C];
__device__ int   g_ofs[C];
__device__ int   g_cur[C];
__device__ int   g_idx[NMAX];
__device__ float g_quad[NMAX * C];

__device__ __forceinline__ float to_tf32(float v) {
    uint32_t t;
    asm("cvt.rna.tf32.f32 %0, %1;" : "=r"(t) : "f"(v));
    return __uint_as_float(t);
}

#define MMA_TF32(acc, a0, a1, a2, a3, b0, b1)                                 \
    asm volatile(                                                             \
        "mma.sync.aligned.m16n8k8.row.col.f32.tf32.tf32.f32 "                 \
        "{%0,%1,%2,%3}, {%4,%5,%6,%7}, {%8,%9}, {%0,%1,%2,%3};"               \
        : "+f"(acc[0]), "+f"(acc[1]), "+f"(acc[2]), "+f"(acc[3])              \
        : "r"(a0), "r"(a1), "r"(a2), "r"(a3), "r"(b0), "r"(b1))

// ---------------------------------------------------------------------------
__global__ void k_zero(int mc) {
    int t = blockIdx.x * blockDim.x + threadIdx.x;
    if (t < C) { g_cnt[t] = 0; g_cur[t] = 0; }
    if (t < mc) g_quad[t] = 0.f;
}

__global__ void k_count(const int* __restrict__ y, int n) {
    int t = blockIdx.x * blockDim.x + threadIdx.x;
    if (t < n) atomicAdd(&g_cnt[y[t]], 1);
}

__global__ void k_scan() {
    int s = 0;
    for (int c = 0; c < C; c++) { g_ofs[c] = s; s += g_cnt[c]; }
}

__global__ void k_fill(const int* __restrict__ y, int n) {
    int t = blockIdx.x * blockDim.x + threadIdx.x;
    if (t < n) {
        int c = y[t];
        int pos = atomicAdd(&g_cur[c], 1);
        g_idx[g_ofs[c] + pos] = t;
    }
}

// gather rows of X into class-sorted g_Xs
__global__ void k_gather(const float* __restrict__ X) {
    int b = blockIdx.x;
    int src = g_idx[b];
    const float4* s = (const float4*)&X[(size_t)src * D];
    float4* d = (float4*)&g_Xs[(size_t)b * D];
    for (int t = threadIdx.x; t < D / 4; t += blockDim.x) d[t] = s[t];
}

// per-class column sums -> mu (reads gathered, contiguous rows)
__global__ void k_mu(const float* __restrict__ m, const float* __restrict__ kappa) {
    int c = blockIdx.y;
    int j = blockIdx.x * blockDim.x + threadIdx.x;
    if (j >= D) return;
    int ofs = g_ofs[c], n = g_cnt[c];
    float s = 0.f;
    for (int r = 0; r < n; r++)
        s += g_Xs[(size_t)(ofs + r) * D + j];
    float kap = fabsf(kappa[0]) + 1e-6f;
    g_mu[c * D + j] = (kap * m[j] + s) / (kap + (float)n);
}

__global__ void k_munorm() {
    int c = blockIdx.x, lane = threadIdx.x;
    float s = 0.f;
    for (int k = lane; k < D; k += 32) { float v = g_mu[c * D + k]; s += v * v; }
    for (int o = 16; o; o >>= 1) s += __shfl_xor_sync(0xffffffffu, s, o);
    if (lane == 0) g_munorm[c] = s;
}

// build L^T:  Lt[k*D+i] = (i==k ? |diag_i| : (i>k ? low[i][k] : 0))
__global__ void k_Lt(const float* __restrict__ tdiag, const float* __restrict__ tlow) {
    int e = blockIdx.x * blockDim.x + threadIdx.x;
    if (e >= D * D) return;
    int i = e % D, k = e / D;
    float v = 0.f;
    if (i == k) v = fabsf(tdiag[i]);
    else if (i > k) v = tlow[(size_t)i * D + k];
    g_Lt[e] = v;
}

// ---------------------------------------------------------------------------
// AtA via tensor cores, 3xTF32 split, double-buffered smem + reg prefetch.
// Lower-triangular tiles only (ib >= jb); upper-tile blocks exit immediately.
// z < C:  S[c] lower -> g_sigma[c] ;  z == C: base lower -> g_base
#define SKT 16
__global__ __launch_bounds__(256) void k_ssyrk_tc() {
    __shared__ float sAh[2][SKT][132], sAl[2][SKT][132];
    __shared__ float sBh[2][SKT][132], sBl[2][SKT][132];
    int ib = blockIdx.x, jb = blockIdx.y, z = blockIdx.z;
    if (ib < jb) return;                       // consumers never read upper tiles
    int tid = threadIdx.x, wid = tid >> 5, lane = tid & 31;
    int wm = wid >> 1, wn = wid & 1;
    int gID = lane >> 2, tig = lane & 3;
    int i0 = ib * 128, j0 = jb * 128;
    const float* src;
    float* out;
    int ofs, n;
    if (z < C) { src = g_Xs; ofs = g_ofs[z]; n = g_cnt[z]; out = g_sigma + (size_t)z * D * D; }
    else       { src = g_Lt; ofs = 0;       n = D;        out = g_base; }
    float acc[2][8][4] = {};
    int nchunks = (n + SKT - 1) / SKT;

    int sl_isB[4], sl_rr[4], sl_c4[4];
    #pragma unroll
    for (int l = 0; l < 4; l++) {
        int e = tid + l * 256;
        sl_isB[l] = e >> 9;
        int idx = e & 511;
        sl_rr[l] = idx >> 5;
        sl_c4[l] = (idx & 31) * 4;
    }
    float4 pf[4];

    #define SSYRK_LOAD(R0)                                                     \
        _Pragma("unroll")                                                      \
        for (int l = 0; l < 4; l++) {                                          \
            pf[l] = make_float4(0.f, 0.f, 0.f, 0.f);                           \
            if ((R0) + sl_rr[l] < n) {                                         \
                int col0 = (sl_isB[l] ? j0 : i0) + sl_c4[l];                   \
                pf[l] = *(const float4*)&src[(size_t)(ofs + (R0) + sl_rr[l]) * D + col0]; \
            }                                                                  \
        }

    #define SSYRK_STORE(BUF)                                                   \
        _Pragma("unroll")                                                      \
        for (int l = 0; l < 4; l++) {                                          \
            float* Hh = sl_isB[l] ? &sBh[BUF][sl_rr[l]][sl_c4[l]] : &sAh[BUF][sl_rr[l]][sl_c4[l]]; \
            float* Hl = sl_isB[l] ? &sBl[BUF][sl_rr[l]][sl_c4[l]] : &sAl[BUF][sl_rr[l]][sl_c4[l]]; \
            float h;                                                           \
            h = to_tf32(pf[l].x); Hh[0] = h; Hl[0] = to_tf32(pf[l].x - h);     \
            h = to_tf32(pf[l].y); Hh[1] = h; Hl[1] = to_tf32(pf[l].y - h);     \
            h = to_tf32(pf[l].z); Hh[2] = h; Hl[2] = to_tf32(pf[l].z - h);     \
            h = to_tf32(pf[l].w); Hh[3] = h; Hl[3] = to_tf32(pf[l].w - h);     \
        }

    SSYRK_LOAD(0);
    SSYRK_STORE(0);
    __syncthreads();
    for (int ch = 0; ch < nchunks; ch++) {
        if (ch + 1 < nchunks) { SSYRK_LOAD((ch + 1) * SKT); }
        int buf = ch & 1;
        #pragma unroll
        for (int ks = 0; ks < SKT; ks += 8) {
            uint32_t bh[8][2], bl[8][2];
            #pragma unroll
            for (int nt = 0; nt < 8; nt++) {
                int col = wn * 64 + nt * 8 + gID;
                bh[nt][0] = __float_as_uint(sBh[buf][ks + tig][col]);
                bh[nt][1] = __float_as_uint(sBh[buf][ks + tig + 4][col]);
                bl[nt][0] = __float_as_uint(sBl[buf][ks + tig][col]);
                bl[nt][1] = __float_as_uint(sBl[buf][ks + tig + 4][col]);
            }
            #pragma unroll
            for (int mt = 0; mt < 2; mt++) {
                int row = wm * 32 + mt * 16;
                uint32_t ah0 = __float_as_uint(sAh[buf][ks + tig][row + gID]);
                uint32_t ah1 = __float_as_uint(sAh[buf][ks + tig][row + gID + 8]);
                uint32_t ah2 = __float_as_uint(sAh[buf][ks + tig + 4][row + gID]);
                uint32_t ah3 = __float_as_uint(sAh[buf][ks + tig + 4][row + gID + 8]);
                uint32_t al0 = __float_as_uint(sAl[buf][ks + tig][row + gID]);
                uint32_t al1 = __float_as_uint(sAl[buf][ks + tig][row + gID + 8]);
                uint32_t al2 = __float_as_uint(sAl[buf][ks + tig + 4][row + gID]);
                uint32_t al3 = __float_as_uint(sAl[buf][ks + tig + 4][row + gID + 8]);
                #pragma unroll
                for (int nt = 0; nt < 8; nt++) {
                    MMA_TF32(acc[mt][nt], ah0, ah1, ah2, ah3, bh[nt][0], bh[nt][1]);
                    MMA_TF32(acc[mt][nt], ah0, ah1, ah2, ah3, bl[nt][0], bl[nt][1]);
                    MMA_TF32(acc[mt][nt], al0, al1, al2, al3, bh[nt][0], bh[nt][1]);
                }
            }
        }
        __syncthreads();
        if (ch + 1 < nchunks) {
            SSYRK_STORE((ch + 1) & 1);
            __syncthreads();
        }
    }
    #pragma unroll
    for (int mt = 0; mt < 2; mt++)
        #pragma unroll
        for (int nt = 0; nt < 8; nt++) {
            int row = i0 + wm * 32 + mt * 16 + gID;
            int col = j0 + wn * 64 + nt * 8 + tig * 2;
            out[(size_t)row * D + col]           = acc[mt][nt][0];
            out[(size_t)row * D + col + 1]       = acc[mt][nt][1];
            out[(size_t)(row + 8) * D + col]     = acc[mt][nt][2];
            out[(size_t)(row + 8) * D + col + 1] = acc[mt][nt][3];
        }
}

// sigma = (S + base + kap m m^T - (kap+Nj) mu mu^T) / (nu_ + Nj + d + 2)
// lower triangle only — downstream never reads the upper part.
__global__ void k_assemble(const float* __restrict__ m,
                           const float* __restrict__ kappa,
                           const float* __restrict__ nu) {
    int c = blockIdx.y;
    int e = blockIdx.x * blockDim.x + threadIdx.x;
    if (e >= D * D) return;
    int i = e / D, j = e % D;
    if (j > i) return;
    float kap = fabsf(kappa[0]) + 1e-6f;
    float nj = (float)g_cnt[c];
    float nu_ = fmaxf(nu[0], (float)(D - 1) + 1e-6f);
    float scale = 1.f / (nu_ + nj + (float)D + 2.f);
    float coef = kap + nj;
    size_t o = (size_t)c * D * D + e;
    g_sigma[o] = (g_sigma[o] + g_base[e] + kap * m[i] * m[j]
                  - coef * g_mu[c * D + i] * g_mu[c * D + j]) * scale;
}

// Cholesky factor of the 64x64 diag block (factor only; no inverse)
__global__ void k_potf2(int kstep) {
    __shared__ float As[NB][NB + 1];
    int c = blockIdx.x, tid = threadIdx.x;
    size_t base = (size_t)c * D * D + (size_t)(kstep * NB) * D + kstep * NB;
    for (int e = tid; e < NB * NB; e += 64)
        As[e / 64][e % 64] = g_sigma[base + (size_t)(e / 64) * D + (e % 64)];
    __syncthreads();
    for (int j = 0; j < NB; j++) {
        if (tid == 0) As[j][j] = sqrtf(As[j][j]);
        __syncthreads();
        if (tid > j) As[tid][j] = As[tid][j] / As[j][j];
        __syncthreads();
        if (tid > j) {
            float l = As[tid][j];
            for (int p = j + 1; p <= tid; p++) As[tid][p] -= l * As[p][j];
        }
        __syncthreads();
    }
    for (int e = tid; e < NB * NB; e += 64) {
        int r = e / 64, cc = e % 64;
        g_sigma[base + (size_t)r * D + cc] = (r >= cc) ? As[r][cc] : 0.f;
    }
}

// panel tile (i,kstep): A <- A * Gkk^{-T} by direct forward substitution
__global__ __launch_bounds__(256) void k_trsolve(int kstep) {
    __shared__ float sG[NB][NB + 1], sX[NB][NB + 1], rd[NB];
    int i = kstep + 1 + blockIdx.x, c = blockIdx.y;
    int tid = threadIdx.x, r = tid & 63, g = tid >> 6;
    size_t gb = (size_t)c * D * D + (size_t)(kstep * NB) * D + kstep * NB;
    size_t ab = (size_t)c * D * D + (size_t)(i * NB) * D + kstep * NB;
    for (int e = tid; e < NB * NB; e += 256) {
        sG[e / 64][e % 64] = g_sigma[gb + (size_t)(e / 64) * D + (e % 64)];
        sX[e / 64][e % 64] = g_sigma[ab + (size_t)(e / 64) * D + (e % 64)];
    }
    __syncthreads();
    if (tid < NB) rd[tid] = 1.f / sG[tid][tid];
    __syncthreads();
    for (int j = 0; j < NB; j++) {
        if (g == 0) sX[r][j] *= rd[j];
        __syncthreads();
        float xj = sX[r][j];
        for (int p = j + 1 + g; p < NB; p += 4)
            sX[r][p] -= xj * sG[p][j];
        __syncthreads();
    }
    for (int e = tid; e < NB * NB; e += 256)
        g_sigma[ab + (size_t)(e / 64) * D + (e % 64)] = sX[e / 64][e % 64];
}

// trailing update: A[i][j] -= Panel_i Panel_j^T (tensor, 3xTF32, 64x64 tiles)
__global__ __launch_bounds__(128) void k_syrkstep_tc(int kstep) {
    __shared__ float sAh[64][20], sAl[64][20], sBh[64][20], sBl[64][20];
    int t = blockIdx.x, c = blockIdx.y;
    int a = 0;
    while ((a + 1) * (a + 2) / 2 <= t) a++;
    int b = t - a * (a + 1) / 2;
    int i = kstep + 1 + a, j = kstep + 1 + b;
    int tid = threadIdx.x, wid = tid >> 5, lane = tid & 31;
    int wm = wid >> 1, wn = wid & 1;
    int gID = lane >> 2, tig = lane & 3;
    size_t ik = (size_t)c * D * D + (size_t)(i * NB) * D + kstep * NB;
    size_t jk = (size_t)c * D * D + (size_t)(j * NB) * D + kstep * NB;
    size_t ij = (size_t)c * D * D + (size_t)(i * NB) * D + j * NB;
    float acc[2][4][4] = {};
    for (int k0 = 0; k0 < NB; k0 += 16) {
        #pragma unroll
        for (int l = 0; l < 2; l++) {
            int e = tid + l * 128;
            int row = e >> 2, k4 = (e & 3) * 4;
            float4 v = *(const float4*)&g_sigma[ik + (size_t)row * D + k0 + k4];
            float h;
            h = to_tf32(v.x); sAh[row][k4 + 0] = h; sAl[row][k4 + 0] = to_tf32(v.x - h);
            h = to_tf32(v.y); sAh[row][k4 + 1] = h; sAl[row][k4 + 1] = to_tf32(v.y - h);
            h = to_tf32(v.z); sAh[row][k4 + 2] = h; sAl[row][k4 + 2] = to_tf32(v.z - h);
            h = to_tf32(v.w); sAh[row][k4 + 3] = h; sAl[row][k4 + 3] = to_tf32(v.w - h);
            float4 w = *(const float4*)&g_sigma[jk + (size_t)row * D + k0 + k4];
            h = to_tf32(w.x); sBh[row][k4 + 0] = h; sBl[row][k4 + 0] = to_tf32(w.x - h);
            h = to_tf32(w.y); sBh[row][k4 + 1] = h; sBl[row][k4 + 1] = to_tf32(w.y - h);
            h = to_tf32(w.z); sBh[row][k4 + 2] = h; sBl[row][k4 + 2] = to_tf32(w.z - h);
            h = to_tf32(w.w); sBh[row][k4 + 3] = h; sBl[row][k4 + 3] = to_tf32(w.w - h);
        }
        __syncthreads();
        #pragma unroll
        for (int ks = 0; ks < 16; ks += 8) {
            uint32_t bh[4][2], bl[4][2];
            #pragma unroll
            for (int nt = 0; nt < 4; nt++) {
                int nb = wn * 32 + nt * 8 + gID;
                bh[nt][0] = __float_as_uint(sBh[nb][ks + tig]);
                bh[nt][1] = __float_as_uint(sBh[nb][ks + tig + 4]);
                bl[nt][0] = __float_as_uint(sBl[nb][ks + tig]);
                bl[nt][1] = __float_as_uint(sBl[nb][ks + tig + 4]);
            }
            #pragma unroll
            for (int mt = 0; mt < 2; mt++) {
                int mr = wm * 32 + mt * 16 + gID;
                uint32_t ah0 = __float_as_uint(sAh[mr][ks + tig]);
                uint32_t ah1 = __float_as_uint(sAh[mr + 8][ks + tig]);
                uint32_t ah2 = __float_as_uint(sAh[mr][ks + tig + 4]);
                uint32_t ah3 = __float_as_uint(sAh[mr + 8][ks + tig + 4]);
                uint32_t al0 = __float_as_uint(sAl[mr][ks + tig]);
                uint32_t al1 = __float_as_uint(sAl[mr + 8][ks + tig]);
                uint32_t al2 = __float_as_uint(sAl[mr][ks + tig + 4]);
                uint32_t al3 = __float_as_uint(sAl[mr + 8][ks + tig + 4]);
                #pragma unroll
                for (int nt = 0; nt < 4; nt++) {
                    MMA_TF32(acc[mt][nt], ah0, ah1, ah2, ah3, bh[nt][0], bh[nt][1]);
                    MMA_TF32(acc[mt][nt], ah0, ah1, ah2, ah3, bl[nt][0], bl[nt][1]);
                    MMA_TF32(acc[mt][nt], al0, al1, al2, al3, bh[nt][0], bh[nt][1]);
                }
            }
        }
        __syncthreads();
    }
    #pragma unroll
    for (int mt = 0; mt < 2; mt++)
        #pragma unroll
        for (int nt = 0; nt < 4; nt++) {
            int row = wm * 32 + mt * 16 + gID;
            int col = wn * 32 + nt * 8 + tig * 2;
            size_t o0 = ij + (size_t)row * D + col;
            size_t o1 = ij + (size_t)(row + 8) * D + col;
            g_sigma[o0]     -= acc[mt][nt][0];
            g_sigma[o0 + 1] -= acc[mt][nt][1];
            g_sigma[o1]     -= acc[mt][nt][2];
            g_sigma[o1 + 1] -= acc[mt][nt][3];
        }
}

// zero all of W (upper blocks must read as true zeros)
__global__ void k_wzero() {
    size_t t = (size_t)blockIdx.x * blockDim.x + threadIdx.x;
    float4 z = make_float4(0.f, 0.f, 0.f, 0.f);
    ((float4*)g_W)[t] = z;
}

// all 64x64 diag-block triangular inverses -> W diag blocks (one launch)
__global__ void k_tinv() {
    __shared__ float As[NB][NB + 1], Inv[NB][NB + 1];
    int kk = blockIdx.x, c = blockIdx.y, tid = threadIdx.x;
    size_t base = (size_t)c * D * D + (size_t)(kk * NB) * D + kk * NB;
    for (int e = tid; e < NB * NB; e += 64) {
        As[e / 64][e % 64] = g_sigma[base + (size_t)(e / 64) * D + (e % 64)];
        Inv[e / 64][e % 64] = 0.f;
    }
    __syncthreads();
    {
        int cc = tid;
        for (int i = cc; i < NB; i++) {
            float s = (i == cc) ? 1.f : 0.f;
            for (int p = cc; p < i; p++) s -= As[i][p] * Inv[p][cc];
            Inv[i][cc] = s / As[i][i];
        }
    }
    __syncthreads();
    for (int e = tid; e < NB * NB; e += 64)
        g_W[base + (size_t)(e / 64) * D + (e % 64)] = Inv[e / 64][e % 64];
}

// -------- recursive-doubling block inverse (tensor, 3xTF32) ----------------
// phase 0: T = G21 * W11  (W11 lower => k starts at tj*64)
// phase 1: W21 = -W22 * T (W22 lower => k ends at (ti+1)*64)
__global__ __launch_bounds__(128) void k_dblmm(int s, int npairs, int phase) {
    __shared__ float sAh[64][20], sAl[64][20];
    __shared__ float sBh[16][68], sBl[16][68];
    int z = blockIdx.z, c = z / npairs, p = z % npairs;
    int ti = blockIdx.x, tj = blockIdx.y;
    int o = p * 2 * s;
    int tid = threadIdx.x, wid = tid >> 5, lane = tid & 31;
    int wm = wid >> 1, wn = wid & 1;
    int gID = lane >> 2, tig = lane & 3;
    const float* Arow;
    const float* Bbase;
    int ldB;
    float* T = g_T + ((size_t)(c * npairs + p)) * s * s;
    if (phase == 0) {
        Arow  = g_sigma + (size_t)c * D * D + (size_t)(o + s + ti * 64) * D + o;
        Bbase = g_W + (size_t)c * D * D + (size_t)o * D + o + tj * 64;
        ldB = D;
    } else {
        Arow  = g_W + (size_t)c * D * D + (size_t)(o + s + ti * 64) * D + (o + s);
        Bbase = T + tj * 64;
        ldB = s;
    }
    int klo = (phase == 0) ? tj * 64 : 0;
    int khi = (phase == 0) ? s : ((ti + 1) * 64 < s ? (ti + 1) * 64 : s);
    float acc[2][4][4] = {};
    for (int k0 = klo; k0 < khi; k0 += 16) {
        #pragma unroll
        for (int l = 0; l < 2; l++) {
            int e = tid + l * 128;
            int row = e >> 2, k4 = (e & 3) * 4;
            float4 v = *(const float4*)&Arow[(size_t)row * D + k0 + k4];
            float h;
            h = to_tf32(v.x); sAh[row][k4 + 0] = h; sAl[row][k4 + 0] = to_tf32(v.x - h);
            h = to_tf32(v.y); sAh[row][k4 + 1] = h; sAl[row][k4 + 1] = to_tf32(v.y - h);
            h = to_tf32(v.z); sAh[row][k4 + 2] = h; sAl[row][k4 + 2] = to_tf32(v.z - h);
            h = to_tf32(v.w); sAh[row][k4 + 3] = h; sAl[row][k4 + 3] = to_tf32(v.w - h);
            int kk = e >> 4, n4 = (e & 15) * 4;
            float4 w = *(const float4*)&Bbase[(size_t)(k0 + kk) * ldB + n4];
            h = to_tf32(w.x); sBh[kk][n4 + 0] = h; sBl[kk][n4 + 0] = to_tf32(w.x - h);
            h = to_tf32(w.y); sBh[kk][n4 + 1] = h; sBl[kk][n4 + 1] = to_tf32(w.y - h);
            h = to_tf32(w.z); sBh[kk][n4 + 2] = h; sBl[kk][n4 + 2] = to_tf32(w.z - h);
            h = to_tf32(w.w); sBh[kk][n4 + 3] = h; sBl[kk][n4 + 3] = to_tf32(w.w - h);
        }
        __syncthreads();
        #pragma unroll
        for (int ks = 0; ks < 16; ks += 8) {
            uint32_t bh[4][2], bl[4][2];
            #pragma unroll
            for (int nt = 0; nt < 4; nt++) {
                int col = wn * 32 + nt * 8 + gID;
                bh[nt][0] = __float_as_uint(sBh[ks + tig][col]);
                bh[nt][1] = __float_as_uint(sBh[ks + tig + 4][col]);
                bl[nt][0] = __float_as_uint(sBl[ks + tig][col]);
                bl[nt][1] = __float_as_uint(sBl[ks + tig + 4][col]);
            }
            #pragma unroll
            for (int mt = 0; mt < 2; mt++) {
                int mr = wm * 32 + mt * 16 + gID;
                uint32_t ah0 = __float_as_uint(sAh[mr][ks + tig]);
                uint32_t ah1 = __float_as_uint(sAh[mr + 8][ks + tig]);
                uint32_t ah2 = __float_as_uint(sAh[mr][ks + tig + 4]);
                uint32_t ah3 = __float_as_uint(sAh[mr + 8][ks + tig + 4]);
                uint32_t al0 = __float_as_uint(sAl[mr][ks + tig]);
                uint32_t al1 = __float_as_uint(sAl[mr + 8][ks + tig]);
                uint32_t al2 = __float_as_uint(sAl[mr][ks + tig + 4]);
                uint32_t al3 = __float_as_uint(sAl[mr + 8][ks + tig + 4]);
                #pragma unroll
                for (int nt = 0; nt < 4; nt++) {
                    MMA_TF32(acc[mt][nt], ah0, ah1, ah2, ah3, bh[nt][0], bh[nt][1]);
                    MMA_TF32(acc[mt][nt], ah0, ah1, ah2, ah3, bl[nt][0], bl[nt][1]);
                    MMA_TF32(acc[mt][nt], al0, al1, al2, al3, bh[nt][0], bh[nt][1]);
                }
            }
        }
        __syncthreads();
    }
    if (phase == 0) {
        #pragma unroll
        for (int mt = 0; mt < 2; mt++)
            #pragma unroll
            for (int nt = 0; nt < 4; nt++) {
                int row = ti * 64 + wm * 32 + mt * 16 + gID;
                int col = tj * 64 + wn * 32 + nt * 8 + tig * 2;
                T[(size_t)row * s + col]           = acc[mt][nt][0];
                T[(size_t)row * s + col + 1]       = acc[mt][nt][1];
                T[(size_t)(row + 8) * s + col]     = acc[mt][nt][2];
                T[(size_t)(row + 8) * s + col + 1] = acc[mt][nt][3];
            }
    } else {
        float* Wout = g_W + (size_t)c * D * D;
        #pragma unroll
        for (int mt = 0; mt < 2; mt++)
            #pragma unroll
            for (int nt = 0; nt < 4; nt++) {
                int row = o + s + ti * 64 + wm * 32 + mt * 16 + gID;
                int col = o + tj * 64 + wn * 32 + nt * 8 + tig * 2;
                Wout[(size_t)row * D + col]           = -acc[mt][nt][0];
                Wout[(size_t)row * D + col + 1]       = -acc[mt][nt][1];
                Wout[(size_t)(row + 8) * D + col]     = -acc[mt][nt][2];
                Wout[(size_t)(row + 8) * D + col + 1] = -acc[mt][nt][3];
            }
    }
}

// ---------------------------------------------------------------------------
// Y = d @ W^T restricted to i-strip; accumulate sum_i Y[q][i]^2 into g_quad.
// Double-buffered smem + register prefetch to hide global latency.
#define QT 128
#define KT 32
__global__ __launch_bounds__(256) void k_ymm(const float* __restrict__ Xq, int M) {
    __shared__ float sD[2][QT][KT + 4];
    __shared__ float sW[2][QT][KT + 4];
    int qb = blockIdx.x, jb = blockIdx.y, c = blockIdx.z;
    int tid = threadIdx.x;
    int wid = tid >> 5, lane = tid & 31;
    int wm = wid >> 1, wn = wid & 1;
    int gID = lane >> 2, tig = lane & 3;
    int q0 = qb * QT, i0 = jb * QT;
    const float* W = g_W + (size_t)c * D * D;
    const float* muc = g_mu + c * D;
    int nchunks = (jb + 1) * QT / KT;
    float acc[2][8][4] = {};

    int sl_r[4], sl_kk[4];
    #pragma unroll
    for (int l = 0; l < 4; l++) {
        int e = tid + l * 256;
        sl_r[l] = e >> 3;
        sl_kk[l] = (e & 7) * 4;
    }
    float4 pD[4], pM[4], pW[4];

    #define YMM_LOAD(K0)                                                       \
        _Pragma("unroll")                                                      \
        for (int l = 0; l < 4; l++) {                                          \
            pD[l] = *(const float4*)&Xq[(size_t)(q0 + sl_r[l]) * D + (K0) + sl_kk[l]]; \
            pM[l] = *(const float4*)&muc[(K0) + sl_kk[l]];                     \
            pW[l] = *(const float4*)&W[(size_t)(i0 + sl_r[l]) * D + (K0) + sl_kk[l]];  \
        }

    #define YMM_STORE(BUF)                                                     \
        _Pragma("unroll")                                                      \
        for (int l = 0; l < 4; l++) {                                          \
            float* pd = &sD[BUF][sl_r[l]][sl_kk[l]];                           \
            float* pw = &sW[BUF][sl_r[l]][sl_kk[l]];                           \
            pd[0] = to_tf32(pD[l].x - pM[l].x);                                \
            pd[1] = to_tf32(pD[l].y - pM[l].y);                                \
            pd[2] = to_tf32(pD[l].z - pM[l].z);                                \
            pd[3] = to_tf32(pD[l].w - pM[l].w);                                \
            pw[0] = to_tf32(pW[l].x);                                          \
            pw[1] = to_tf32(pW[l].y);                                          \
            pw[2] = to_tf32(pW[l].z);                                          \
            pw[3] = to_tf32(pW[l].w);                                          \
        }

    YMM_LOAD(0);
    YMM_STORE(0);
    __syncthreads();
    for (int ch = 0; ch < nchunks; ch++) {
        if (ch + 1 < nchunks) { YMM_LOAD((ch + 1) * KT); }
        int buf = ch & 1;
        #pragma unroll
        for (int ks = 0; ks < KT; ks += 8) {
            uint32_t bf[8][2];
            #pragma unroll
            for (int nt = 0; nt < 8; nt++) {
                int nb = wn * 64 + nt * 8 + gID;
                bf[nt][0] = __float_as_uint(sW[buf][nb][ks + tig]);
                bf[nt][1] = __float_as_uint(sW[buf][nb][ks + tig + 4]);
            }
            #pragma unroll
            for (int mt = 0; mt < 2; mt++) {
                int r = wm * 32 + mt * 16 + gID;
                uint32_t a0 = __float_as_uint(sD[buf][r][ks + tig]);
                uint32_t a1 = __float_as_uint(sD[buf][r + 8][ks + tig]);
                uint32_t a2 = __float_as_uint(sD[buf][r][ks + tig + 4]);
                uint32_t a3 = __float_as_uint(sD[buf][r + 8][ks + tig + 4]);
                #pragma unroll
                for (int nt = 0; nt < 8; nt++) {
                    MMA_TF32(acc[mt][nt], a0, a1, a2, a3, bf[nt][0], bf[nt][1]);
                }
            }
        }
        __syncthreads();
        if (ch + 1 < nchunks) {
            YMM_STORE((ch + 1) & 1);
            __syncthreads();
        }
    }
    float rs[2][2];
    #pragma unroll
    for (int mt = 0; mt < 2; mt++) {
        rs[mt][0] = 0.f; rs[mt][1] = 0.f;
        #pragma unroll
        for (int nt = 0; nt < 8; nt++) {
            rs[mt][0] += acc[mt][nt][0] * acc[mt][nt][0] + acc[mt][nt][1] * acc[mt][nt][1];
            rs[mt][1] += acc[mt][nt][2] * acc[mt][nt][2] + acc[mt][nt][3] * acc[mt][nt][3];
        }
    }
    #pragma unroll
    for (int o = 1; o <= 2; o <<= 1) {
        rs[0][0] += __shfl_xor_sync(0xffffffffu, rs[0][0], o);
        rs[0][1] += __shfl_xor_sync(0xffffffffu, rs[0][1], o);
        rs[1][0] += __shfl_xor_sync(0xffffffffu, rs[1][0], o);
        rs[1][1] += __shfl_xor_sync(0xffffffffu, rs[1][1], o);
    }
    if (tig == 0) {
        #pragma unroll
        for (int mt = 0; mt < 2; mt++) {
            #pragma unroll
            for (int h = 0; h < 2; h++) {
                int q = q0 + wm * 32 + mt * 16 + gID + h * 8;
                atomicAdd(&g_quad[(size_t)q * C + c], rs[mt][h]);
            }
        }
    }
}

// out[q][c] = -(0.9*quad + 0.1*(||x||^2 - 2 x.mu + ||mu||^2))
__global__ __launch_bounds__(256) void k_final(const float* __restrict__ Xq,
                                               float* __restrict__ out) {
    __shared__ float sx[D];
    __shared__ float sqn[8];
    int q = blockIdx.x, tid = threadIdx.x, wid = tid >> 5, lane = tid & 31;
    const float* xr = Xq + (size_t)q * D;
    float pn = 0.f;
    for (int k = tid; k < D; k += 256) { float v = xr[k]; sx[k] = v; pn += v * v; }
    for (int o = 16; o; o >>= 1) pn += __shfl_xor_sync(0xffffffffu, pn, o);
    if (lane == 0) sqn[wid] = pn;
    __syncthreads();
    float qn = 0.f;
    #pragma unroll
    for (int w = 0; w < 8; w++) qn += sqn[w];
    for (int c = wid; c < C; c += 8) {
        const float* muc = g_mu + c * D;
        float ds = 0.f;
        for (int k = lane; k < D; k += 32) ds += sx[k] * muc[k];
        for (int o = 16; o; o >>= 1) ds += __shfl_xor_sync(0xffffffffu, ds, o);
        if (lane == 0) {
            float n2 = qn - 2.f * ds + g_munorm[c];
            out[(size_t)q * C + c] = -(0.9f * g_quad[(size_t)q * C + c] + 0.1f * n2);
        }
    }
}

// ---------------------------------------------------------------------------
extern "C" void kernel_launch(void* const* d_in, const int* in_sizes, int n_in,
                              void* d_out, int out_size) {
    const float* X     = (const float*)d_in[0];
    const int*   y     = (const int*)  d_in[1];
    const float* Xq    = (const float*)d_in[2];
    const float* m     = (const float*)d_in[3];
    const float* kappa = (const float*)d_in[4];
    const float* nu    = (const float*)d_in[5];
    const float* tdiag = (const float*)d_in[6];
    const float* tlow  = (const float*)d_in[7];
    float* out = (float*)d_out;
    int N = in_sizes[1];
    int M = in_sizes[2] / D;

    k_zero<<<(M * C + 255) / 256, 256>>>(M * C);
    k_count<<<(N + 255) / 256, 256>>>(y, N);
    k_scan<<<1, 1>>>();
    k_fill<<<(N + 255) / 256, 256>>>(y, N);
    k_gather<<<N, 256>>>(X);
    k_mu<<<dim3((D + 255) / 256, C), 256>>>(m, kappa);
    k_munorm<<<C, 32>>>();
    k_Lt<<<(D * D + 255) / 256, 256>>>(tdiag, tlow);
    k_ssyrk_tc<<<dim3(D / 128, D / 128, C + 1), 256>>>();
    k_assemble<<<dim3(D * D / 256, C), 256>>>(m, kappa, nu);

    k_wzero<<<(C * D * D / 4) / 256, 256>>>();
    for (int k = 0; k < NBLK; k++) {
        k_potf2<<<C, 64>>>(k);
        int rows = NBLK - 1 - k;
        if (rows > 0) {
            k_trsolve<<<dim3(rows, C), 256>>>(k);
            k_syrkstep_tc<<<dim3(rows * (rows + 1) / 2, C), 128>>>(k);
        }
    }
    k_tinv<<<dim3(NBLK, C), 64>>>();
    for (int l = 0; l < 4; l++) {
        int s = 64 << l;
        int npairs = D / (2 * s);
        k_dblmm<<<dim3(s / 64, s / 64, C * npairs), 128>>>(s, npairs, 0);
        k_dblmm<<<dim3(s / 64, s / 64, C * npairs), 128>>>(s, npairs, 1);
    }

    k_ymm<<<dim3(M / QT, D / QT, C), 256>>>(Xq, M);
    k_final<<<M, 256>>>(Xq, out);
}